// round 1
// baseline (speedup 1.0000x reference)
#include <cuda_runtime.h>
#include <math.h>

// Problem constants (fixed shapes from reference)
#define BB    4
#define TT    8192
#define CC    1024
#define MROWS (BB * TT)      // 32768
#define NCH   64
#define CHUNK 128            // NCH * CHUNK == TT

// -------- scratch (device globals; no runtime allocation allowed) --------
__device__ float g_xx [(size_t)MROWS * CC];
__device__ float g_k  [(size_t)MROWS * CC];
__device__ float g_v  [(size_t)MROWS * CC];
__device__ float g_r  [(size_t)MROWS * CC];
__device__ float g_att[(size_t)MROWS * CC];
__device__ float g_csum[(size_t)BB * NCH * CC];

// ======================= LayerNorm: one warp per row =======================
__global__ void ln_kernel(const float* __restrict__ x,
                          const float* __restrict__ ln_w,
                          const float* __restrict__ ln_b) {
    int gwarp = (blockIdx.x * blockDim.x + threadIdx.x) >> 5;
    int lane  = threadIdx.x & 31;
    if (gwarp >= MROWS) return;

    const float4* xr = (const float4*)(x + (size_t)gwarp * CC);
    const float4* wr = (const float4*)ln_w;
    const float4* br = (const float4*)ln_b;
    float4* orow = (float4*)(g_xx + (size_t)gwarp * CC);

    float4 vals[8];
    float s = 0.f, s2 = 0.f;
#pragma unroll
    for (int i = 0; i < 8; i++) {
        float4 v = xr[lane + i * 32];
        vals[i] = v;
        s  += v.x + v.y + v.z + v.w;
        s2 += v.x * v.x + v.y * v.y + v.z * v.z + v.w * v.w;
    }
#pragma unroll
    for (int off = 16; off; off >>= 1) {
        s  += __shfl_xor_sync(0xffffffffu, s,  off);
        s2 += __shfl_xor_sync(0xffffffffu, s2, off);
    }
    const float inv = 1.0f / (float)CC;
    float mu  = s * inv;
    float var = s2 * inv - mu * mu;
    float rstd = rsqrtf(var + 1e-5f);

#pragma unroll
    for (int i = 0; i < 8; i++) {
        float4 v = vals[i];
        float4 w = wr[lane + i * 32];
        float4 b = br[lane + i * 32];
        float4 o;
        o.x = (v.x - mu) * rstd * w.x + b.x;
        o.y = (v.y - mu) * rstd * w.y + b.y;
        o.z = (v.z - mu) * rstd * w.z + b.z;
        o.w = (v.w - mu) * rstd * w.w + b.w;
        orow[lane + i * 32] = o;
    }
}

// ================= fp32 NT GEMM: C[M,N] = A[M,K] * W[N,K]^T =================
// 128x128 block tile, BK=8, 256 threads, 8x8 per thread.
__device__ __forceinline__ void gemm_body(const float* __restrict__ A,
                                          const float* __restrict__ W,
                                          float* __restrict__ Cm) {
    __shared__ __align__(16) float As[8][128];
    __shared__ __align__(16) float Bs[8][128];

    const int tid  = threadIdx.x;
    const int brow = blockIdx.y * 128;
    const int bcol = blockIdx.x * 128;
    const int lr = tid >> 1;          // 0..127
    const int lc = (tid & 1) << 2;    // 0 or 4
    const int ty = tid >> 4;          // 0..15
    const int tx = tid & 15;          // 0..15

    const float* Ap = A + (size_t)(brow + lr) * CC + lc;
    const float* Wp = W + (size_t)(bcol + lr) * CC + lc;

    float acc[8][8];
#pragma unroll
    for (int i = 0; i < 8; i++)
#pragma unroll
        for (int j = 0; j < 8; j++) acc[i][j] = 0.f;

    for (int k0 = 0; k0 < CC; k0 += 8) {
        float4 a = *(const float4*)(Ap + k0);
        float4 b = *(const float4*)(Wp + k0);
        As[lc + 0][lr] = a.x; As[lc + 1][lr] = a.y;
        As[lc + 2][lr] = a.z; As[lc + 3][lr] = a.w;
        Bs[lc + 0][lr] = b.x; Bs[lc + 1][lr] = b.y;
        Bs[lc + 2][lr] = b.z; Bs[lc + 3][lr] = b.w;
        __syncthreads();
#pragma unroll
        for (int kk = 0; kk < 8; kk++) {
            float4 a0 = *(const float4*)&As[kk][ty * 8];
            float4 a1 = *(const float4*)&As[kk][ty * 8 + 4];
            float4 b0 = *(const float4*)&Bs[kk][tx * 8];
            float4 b1 = *(const float4*)&Bs[kk][tx * 8 + 4];
            float ar[8] = {a0.x, a0.y, a0.z, a0.w, a1.x, a1.y, a1.z, a1.w};
            float br[8] = {b0.x, b0.y, b0.z, b0.w, b1.x, b1.y, b1.z, b1.w};
#pragma unroll
            for (int i = 0; i < 8; i++)
#pragma unroll
                for (int j = 0; j < 8; j++)
                    acc[i][j] += ar[i] * br[j];
        }
        __syncthreads();
    }

#pragma unroll
    for (int i = 0; i < 8; i++) {
        float* cp = Cm + (size_t)(brow + ty * 8 + i) * CC + bcol + tx * 8;
        *(float4*)(cp)     = make_float4(acc[i][0], acc[i][1], acc[i][2], acc[i][3]);
        *(float4*)(cp + 4) = make_float4(acc[i][4], acc[i][5], acc[i][6], acc[i][7]);
    }
}

__global__ __launch_bounds__(256, 2) void gemm_kvr(const float* __restrict__ Wk,
                                                   const float* __restrict__ Wv,
                                                   const float* __restrict__ Wr) {
    const float* W = (blockIdx.z == 0) ? Wk : (blockIdx.z == 1) ? Wv : Wr;
    float* Cm      = (blockIdx.z == 0) ? g_k : (blockIdx.z == 1) ? g_v : g_r;
    gemm_body(g_xx, W, Cm);
}

__global__ __launch_bounds__(256, 2) void gemm_wo(const float* __restrict__ Wo,
                                                  float* __restrict__ out) {
    gemm_body(g_att, Wo, out);
}

// ======================= WKV scan (chunked 3-pass) =======================
// Pass 1: per-chunk partial sums of kv[t] = k*v*exp(td*t)
__global__ void scan_partial(const float* __restrict__ time_decay) {
    int c  = blockIdx.x * 256 + threadIdx.x;
    int ch = blockIdx.y;
    int b  = blockIdx.z;
    float td = -expf(time_decay[c]);
    size_t base = ((size_t)(b * TT + ch * CHUNK)) * CC + c;
    float s = 0.f;
#pragma unroll 4
    for (int i = 0; i < CHUNK; i++) {
        float t = (float)(ch * CHUNK + i);
        float w = expf(td * t);
        size_t id = base + (size_t)i * CC;
        s += g_k[id] * g_v[id] * w;
    }
    g_csum[((size_t)b * NCH + ch) * CC + c] = s;
}

// Pass 2: exclusive scan over chunk sums per (b,c)
__global__ void scan_offsets() {
    int idx = blockIdx.x * 256 + threadIdx.x;   // 0..4095
    int b = idx >> 10;
    int c = idx & (CC - 1);
    float run = 0.f;
#pragma unroll
    for (int ch = 0; ch < NCH; ch++) {
        size_t id = ((size_t)b * NCH + ch) * CC + c;
        float tmp = g_csum[id];
        g_csum[id] = run;
        run += tmp;
    }
}

// Pass 3: replay with offsets; write att = sigmoid(r) * (hist + k*tf)
__global__ void scan_final(const float* __restrict__ time_decay,
                           const float* __restrict__ time_first) {
    int c  = blockIdx.x * 256 + threadIdx.x;
    int ch = blockIdx.y;
    int b  = blockIdx.z;
    float td = -expf(time_decay[c]);
    float tf = expf(time_first[c]);
    float state = g_csum[((size_t)b * NCH + ch) * CC + c];
    size_t base = ((size_t)(b * TT + ch * CHUNK)) * CC + c;
#pragma unroll 4
    for (int i = 0; i < CHUNK; i++) {
        size_t id = base + (size_t)i * CC;
        float kk = g_k[id];
        float vv = g_v[id];
        float rr = g_r[id];
        float w  = expf(td * (float)(ch * CHUNK + i));
        float sig = 1.0f / (1.0f + expf(-rr));
        g_att[id] = sig * (state + kk * tf);
        state += kk * vv * w;
    }
}

// ================================ launch ================================
extern "C" void kernel_launch(void* const* d_in, const int* in_sizes, int n_in,
                              void* d_out, int out_size) {
    const float* x          = (const float*)d_in[0];
    const float* time_decay = (const float*)d_in[1];
    const float* time_first = (const float*)d_in[2];
    const float* Wk         = (const float*)d_in[3];
    const float* Wv         = (const float*)d_in[4];
    const float* Wr         = (const float*)d_in[5];
    const float* Wo         = (const float*)d_in[6];
    const float* ln_w       = (const float*)d_in[7];
    const float* ln_b       = (const float*)d_in[8];
    float* out = (float*)d_out;

    // 1) LayerNorm -> g_xx
    ln_kernel<<<MROWS / 8, 256>>>(x, ln_w, ln_b);

    // 2) k, v, r projections (three 32768x1024x1024 NT GEMMs, fused by blockIdx.z)
    gemm_kvr<<<dim3(CC / 128, MROWS / 128, 3), 256>>>(Wk, Wv, Wr);

    // 3) WKV scan (chunked over T)
    scan_partial<<<dim3(CC / 256, NCH, BB), 256>>>(time_decay);
    scan_offsets<<<(BB * CC) / 256, 256>>>();
    scan_final<<<dim3(CC / 256, NCH, BB), 256>>>(time_decay, time_first);

    // 4) output projection -> d_out
    gemm_wo<<<dim3(CC / 128, MROWS / 128), 256>>>(Wo, out);
}

// round 4
// speedup vs baseline: 2.3583x; 2.3583x over previous
#include <cuda_runtime.h>
#include <cuda_bf16.h>
#include <math.h>
#include <stdint.h>

// ----------------------------- problem constants -----------------------------
#define BB    4
#define TT    8192
#define CC    1024
#define MROWS (BB * TT)       // 32768
#define KP    3072            // split-K: A'=[hi|lo|hi], W'=[hi|hi|lo]
#define NCH   64
#define CHUNK 128             // NCH * CHUNK == TT

// GEMM tiling (Ampere-style mma.sync)
#define BM     128
#define BN     128
#define BK     32
#define ROWB   80                       // smem bytes per 32-bf16 row (64B + 16B pad)
#define A_SZ   (BM * ROWB)              // 10240 B
#define STG_SZ (2 * A_SZ)               // A tile + B tile
#define NSTG   3
#define NCHUNKS (KP / BK)               // 96
#define SMEM_DYN (NSTG * STG_SZ)        // 61440 B

// -------- scratch (device globals; no runtime allocation allowed) --------
__device__ __nv_bfloat16 g_a   [(size_t)MROWS * KP];   // ln output, split layout
__device__ __nv_bfloat16 g_att2[(size_t)MROWS * KP];   // attention, split layout
__device__ __nv_bfloat16 g_w   [(size_t)4 * CC * KP];  // Wk,Wv,Wr,Wo split layout
__device__ float g_k  [(size_t)MROWS * CC];
__device__ float g_v  [(size_t)MROWS * CC];
__device__ float g_r  [(size_t)MROWS * CC];
__device__ float g_csum[(size_t)BB * NCH * CC];

// ----------------------------- PTX helpers -----------------------------
__device__ __forceinline__ uint32_t smem_u32(const void* p) {
    uint32_t a;
    asm("{ .reg .u64 t; cvta.to.shared.u64 t, %1; cvt.u32.u64 %0, t; }" : "=r"(a) : "l"(p));
    return a;
}
__device__ __forceinline__ void cp16(uint32_t dst, const void* src) {
    asm volatile("cp.async.cg.shared.global [%0], [%1], 16;" :: "r"(dst), "l"(src));
}
__device__ __forceinline__ void cp_commit() {
    asm volatile("cp.async.commit_group;" ::: "memory");
}
__device__ __forceinline__ void cp_wait1() {
    asm volatile("cp.async.wait_group 1;" ::: "memory");
}
__device__ __forceinline__ void ldmA(uint32_t* f, uint32_t addr) {
    asm volatile("ldmatrix.sync.aligned.m8n8.x4.shared.b16 {%0,%1,%2,%3}, [%4];"
                 : "=r"(f[0]), "=r"(f[1]), "=r"(f[2]), "=r"(f[3]) : "r"(addr));
}
__device__ __forceinline__ void ldmB(uint32_t* f, uint32_t addr) {
    asm volatile("ldmatrix.sync.aligned.m8n8.x2.shared.b16 {%0,%1}, [%2];"
                 : "=r"(f[0]), "=r"(f[1]) : "r"(addr));
}
__device__ __forceinline__ void mma16816(float* c, const uint32_t* a, const uint32_t* b) {
    asm volatile("mma.sync.aligned.m16n8k16.row.col.f32.bf16.bf16.f32 "
                 "{%0,%1,%2,%3}, {%4,%5,%6,%7}, {%8,%9}, {%0,%1,%2,%3};"
                 : "+f"(c[0]), "+f"(c[1]), "+f"(c[2]), "+f"(c[3])
                 : "r"(a[0]), "r"(a[1]), "r"(a[2]), "r"(a[3]), "r"(b[0]), "r"(b[1]));
}

// ======================= LayerNorm -> split bf16 layout =======================
__global__ void ln_kernel(const float* __restrict__ x,
                          const float* __restrict__ ln_w,
                          const float* __restrict__ ln_b) {
    int gwarp = (blockIdx.x * blockDim.x + threadIdx.x) >> 5;
    int lane  = threadIdx.x & 31;
    if (gwarp >= MROWS) return;

    const float4* xr = (const float4*)(x + (size_t)gwarp * CC);
    const float4* wr = (const float4*)ln_w;
    const float4* br = (const float4*)ln_b;

    float4 vals[8];
    float s = 0.f, s2 = 0.f;
#pragma unroll
    for (int i = 0; i < 8; i++) {
        float4 v = xr[lane + i * 32];
        vals[i] = v;
        s  += v.x + v.y + v.z + v.w;
        s2 += v.x * v.x + v.y * v.y + v.z * v.z + v.w * v.w;
    }
#pragma unroll
    for (int off = 16; off; off >>= 1) {
        s  += __shfl_xor_sync(0xffffffffu, s,  off);
        s2 += __shfl_xor_sync(0xffffffffu, s2, off);
    }
    const float inv = 1.0f / (float)CC;
    float mu  = s * inv;
    float var = s2 * inv - mu * mu;
    float rstd = rsqrtf(var + 1e-5f);

    __nv_bfloat16* arow = g_a + (size_t)gwarp * KP;
#pragma unroll
    for (int i = 0; i < 8; i++) {
        float4 v = vals[i];
        float4 w = wr[lane + i * 32];
        float4 b = br[lane + i * 32];
        float o0 = (v.x - mu) * rstd * w.x + b.x;
        float o1 = (v.y - mu) * rstd * w.y + b.y;
        float o2 = (v.z - mu) * rstd * w.z + b.z;
        float o3 = (v.w - mu) * rstd * w.w + b.w;
        __nv_bfloat16 h0 = __float2bfloat16_rn(o0);
        __nv_bfloat16 h1 = __float2bfloat16_rn(o1);
        __nv_bfloat16 h2 = __float2bfloat16_rn(o2);
        __nv_bfloat16 h3 = __float2bfloat16_rn(o3);
        __nv_bfloat16 l0 = __float2bfloat16_rn(o0 - __bfloat162float(h0));
        __nv_bfloat16 l1 = __float2bfloat16_rn(o1 - __bfloat162float(h1));
        __nv_bfloat16 l2 = __float2bfloat16_rn(o2 - __bfloat162float(h2));
        __nv_bfloat16 l3 = __float2bfloat16_rn(o3 - __bfloat162float(h3));
        int col = (lane + i * 32) * 4;
        __nv_bfloat162 H0; H0.x = h0; H0.y = h1;
        __nv_bfloat162 H1; H1.x = h2; H1.y = h3;
        __nv_bfloat162 L0; L0.x = l0; L0.y = l1;
        __nv_bfloat162 L1; L1.x = l2; L1.y = l3;
        *(__nv_bfloat162*)(arow + col)            = H0;
        *(__nv_bfloat162*)(arow + col + 2)        = H1;
        *(__nv_bfloat162*)(arow + 1024 + col)     = L0;
        *(__nv_bfloat162*)(arow + 1024 + col + 2) = L1;
        *(__nv_bfloat162*)(arow + 2048 + col)     = H0;
        *(__nv_bfloat162*)(arow + 2048 + col + 2) = H1;
    }
}

// =================== weight conversion to split bf16 layout ===================
__global__ void wconv(const float* __restrict__ Wk, const float* __restrict__ Wv,
                      const float* __restrict__ Wr, const float* __restrict__ Wo) {
    size_t idx  = (size_t)blockIdx.x * blockDim.x + threadIdx.x;
    size_t base = idx * 4;
    int w = (int)(base >> 20);
    size_t rem = base & 0xFFFFFu;
    const float* W = (w == 0) ? Wk : (w == 1) ? Wv : (w == 2) ? Wr : Wo;
    float4 v = *(const float4*)(W + rem);
    __nv_bfloat16 h0 = __float2bfloat16_rn(v.x);
    __nv_bfloat16 h1 = __float2bfloat16_rn(v.y);
    __nv_bfloat16 h2 = __float2bfloat16_rn(v.z);
    __nv_bfloat16 h3 = __float2bfloat16_rn(v.w);
    __nv_bfloat16 l0 = __float2bfloat16_rn(v.x - __bfloat162float(h0));
    __nv_bfloat16 l1 = __float2bfloat16_rn(v.y - __bfloat162float(h1));
    __nv_bfloat16 l2 = __float2bfloat16_rn(v.z - __bfloat162float(h2));
    __nv_bfloat16 l3 = __float2bfloat16_rn(v.w - __bfloat162float(h3));
    size_t row = rem >> 10;          // output row n within this weight
    size_t k   = rem & 1023u;
    __nv_bfloat16* dst = g_w + ((size_t)w * CC + row) * KP + k;
    __nv_bfloat162 H0; H0.x = h0; H0.y = h1;
    __nv_bfloat162 H1; H1.x = h2; H1.y = h3;
    __nv_bfloat162 L0; L0.x = l0; L0.y = l1;
    __nv_bfloat162 L1; L1.x = l2; L1.y = l3;
    *(__nv_bfloat162*)(dst)            = H0;
    *(__nv_bfloat162*)(dst + 2)        = H1;
    *(__nv_bfloat162*)(dst + 1024)     = H0;
    *(__nv_bfloat162*)(dst + 1024 + 2) = H1;
    *(__nv_bfloat162*)(dst + 2048)     = L0;
    *(__nv_bfloat162*)(dst + 2048 + 2) = L1;
}

// ============== bf16 mma.sync NT GEMM: C[M,N] = A'[M,KP] * W'[N,KP]^T ==============
__global__ void __launch_bounds__(256, 2)
gemm_mma(float* __restrict__ out, int isKVR) {
    extern __shared__ __align__(1024) char smem[];
    const uint32_t sbase = smem_u32(smem);

    const int tid  = threadIdx.x;
    const int lane = tid & 31;
    const int wid  = tid >> 5;
    const int wm   = wid & 1;     // 2 warp-rows (64 each)
    const int wn   = wid >> 1;    // 4 warp-cols (32 each)

    int col, w;
    if (isKVR) { w = blockIdx.x % 3; col = blockIdx.x / 3; }
    else       { w = 3;              col = blockIdx.x;     }
    const int brow = blockIdx.y * BM;
    const int bcol = col * BN;

    // FIX (R3): A source depends on which pass this is.
    const __nv_bfloat16* Abase = (isKVR ? g_a : g_att2) + (size_t)brow * KP;
    const __nv_bfloat16* Wbase = g_w + ((size_t)w * CC + bcol) * KP;

    // ldmatrix per-lane offsets (bytes within a tile)
    uint32_t aoff[4], boff[4];
#pragma unroll
    for (int mt = 0; mt < 4; mt++)
        aoff[mt] = (uint32_t)((wm * 64 + mt * 16 + (lane & 15)) * ROWB + ((lane >> 4) << 4));
#pragma unroll
    for (int nt = 0; nt < 4; nt++)
        boff[nt] = (uint32_t)((wn * 32 + nt * 8 + (lane & 7)) * ROWB + (((lane >> 3) & 1) << 4));

    float acc[4][4][4];
#pragma unroll
    for (int mt = 0; mt < 4; mt++)
#pragma unroll
        for (int nt = 0; nt < 4; nt++)
#pragma unroll
            for (int j = 0; j < 4; j++) acc[mt][nt][j] = 0.f;

    // ---- async load of one stage ----
    auto load_stage = [&](int stg, int chunk) {
        uint32_t sA = sbase + stg * STG_SZ;
        uint32_t sB = sA + A_SZ;
        const __nv_bfloat16* Ap = Abase + chunk * BK;
        const __nv_bfloat16* Wp = Wbase + chunk * BK;
#pragma unroll
        for (int t = tid; t < 512; t += 256) {
            int r = t >> 2, c = t & 3;
            cp16(sA + r * ROWB + c * 16, Ap + (size_t)r * KP + c * 8);
            cp16(sB + r * ROWB + c * 16, Wp + (size_t)r * KP + c * 8);
        }
    };

    load_stage(0, 0); cp_commit();
    load_stage(1, 1); cp_commit();

    for (int i = 0; i < NCHUNKS; i++) {
        cp_wait1();
        __syncthreads();
        if (i + 2 < NCHUNKS) load_stage((i + 2) % NSTG, i + 2);
        cp_commit();

        uint32_t sA = sbase + (i % NSTG) * STG_SZ;
        uint32_t sB = sA + A_SZ;
#pragma unroll
        for (int kh = 0; kh < 2; kh++) {
            uint32_t kb = kh * 32;
            uint32_t af[4][4], bf[4][2];
#pragma unroll
            for (int mt = 0; mt < 4; mt++) ldmA(af[mt], sA + aoff[mt] + kb);
#pragma unroll
            for (int nt = 0; nt < 4; nt++) ldmB(bf[nt], sB + boff[nt] + kb);
#pragma unroll
            for (int mt = 0; mt < 4; mt++)
#pragma unroll
                for (int nt = 0; nt < 4; nt++)
                    mma16816(acc[mt][nt], af[mt], bf[nt]);
        }
    }

    // ---- epilogue: fp32 direct to global ----
    float* Cm;
    if (isKVR) Cm = (w == 0) ? g_k : (w == 1) ? g_v : g_r;
    else       Cm = out;
    const int r0 = brow + wm * 64 + (lane >> 2);
    const int c0 = bcol + wn * 32 + (lane & 3) * 2;
#pragma unroll
    for (int mt = 0; mt < 4; mt++) {
#pragma unroll
        for (int nt = 0; nt < 4; nt++) {
            float* p0 = Cm + (size_t)(r0 + mt * 16) * CC + c0 + nt * 8;
            float* p1 = p0 + 8 * CC;
            *(float2*)p0 = make_float2(acc[mt][nt][0], acc[mt][nt][1]);
            *(float2*)p1 = make_float2(acc[mt][nt][2], acc[mt][nt][3]);
        }
    }
}

// ======================= WKV scan (chunked 3-pass) =======================
__global__ void scan_partial(const float* __restrict__ time_decay) {
    int c  = blockIdx.x * 256 + threadIdx.x;
    int ch = blockIdx.y;
    int b  = blockIdx.z;
    float td = -expf(time_decay[c]);
    size_t base = ((size_t)(b * TT + ch * CHUNK)) * CC + c;
    float s = 0.f;
#pragma unroll 4
    for (int i = 0; i < CHUNK; i++) {
        float t = (float)(ch * CHUNK + i);
        float w = expf(td * t);
        size_t id = base + (size_t)i * CC;
        s += g_k[id] * g_v[id] * w;
    }
    g_csum[((size_t)b * NCH + ch) * CC + c] = s;
}

__global__ void scan_offsets() {
    int idx = blockIdx.x * 256 + threadIdx.x;   // 0..4095
    int b = idx >> 10;
    int c = idx & (CC - 1);
    float run = 0.f;
#pragma unroll
    for (int ch = 0; ch < NCH; ch++) {
        size_t id = ((size_t)b * NCH + ch) * CC + c;
        float tmp = g_csum[id];
        g_csum[id] = run;
        run += tmp;
    }
}

__global__ void scan_final(const float* __restrict__ time_decay,
                           const float* __restrict__ time_first) {
    int c  = blockIdx.x * 256 + threadIdx.x;
    int ch = blockIdx.y;
    int b  = blockIdx.z;
    float td = -expf(time_decay[c]);
    float tf = expf(time_first[c]);
    float state = g_csum[((size_t)b * NCH + ch) * CC + c];
    size_t rowbase = (size_t)(b * TT + ch * CHUNK);
#pragma unroll 4
    for (int i = 0; i < CHUNK; i++) {
        size_t id = (rowbase + i) * CC + c;
        float kk = g_k[id];
        float vv = g_v[id];
        float rr = g_r[id];
        float wgt = expf(td * (float)(ch * CHUNK + i));
        float sig = 1.0f / (1.0f + expf(-rr));
        float av  = sig * (state + kk * tf);
        state += kk * vv * wgt;
        __nv_bfloat16 h = __float2bfloat16_rn(av);
        __nv_bfloat16 l = __float2bfloat16_rn(av - __bfloat162float(h));
        __nv_bfloat16* arow = g_att2 + (rowbase + i) * KP + c;
        arow[0]    = h;
        arow[1024] = l;
        arow[2048] = h;
    }
}

// ================================ launch ================================
extern "C" void kernel_launch(void* const* d_in, const int* in_sizes, int n_in,
                              void* d_out, int out_size) {
    const float* x          = (const float*)d_in[0];
    const float* time_decay = (const float*)d_in[1];
    const float* time_first = (const float*)d_in[2];
    const float* Wk         = (const float*)d_in[3];
    const float* Wv         = (const float*)d_in[4];
    const float* Wr         = (const float*)d_in[5];
    const float* Wo         = (const float*)d_in[6];
    const float* ln_w       = (const float*)d_in[7];
    const float* ln_b       = (const float*)d_in[8];
    float* out = (float*)d_out;

    cudaFuncSetAttribute(gemm_mma, cudaFuncAttributeMaxDynamicSharedMemorySize, SMEM_DYN);

    // 1) LayerNorm -> g_a (split bf16); weights -> g_w (split bf16)
    ln_kernel<<<MROWS / 8, 256>>>(x, ln_w, ln_b);
    wconv<<<4096, 256>>>(Wk, Wv, Wr, Wo);

    // 2) k, v, r projections (fused: blockIdx.x = col*3 + weight, w fastest for L2 reuse)
    gemm_mma<<<dim3(24, MROWS / BM), 256, SMEM_DYN>>>(nullptr, 1);

    // 3) WKV scan (chunked over T), emits split-bf16 att
    scan_partial<<<dim3(CC / 256, NCH, BB), 256>>>(time_decay);
    scan_offsets<<<(BB * CC) / 256, 256>>>();
    scan_final<<<dim3(CC / 256, NCH, BB), 256>>>(time_decay, time_first);

    // 4) output projection -> d_out
    gemm_mma<<<dim3(8, MROWS / BM), 256, SMEM_DYN>>>(out, 0);
}

// round 5
// speedup vs baseline: 3.1929x; 1.3539x over previous
#include <cuda_runtime.h>
#include <cuda_bf16.h>
#include <math.h>
#include <stdint.h>

// ----------------------------- problem constants -----------------------------
#define BB    4
#define TT    8192
#define CC    1024
#define MROWS (BB * TT)       // 32768
#define KP    3072            // split-K: A'=[hi|lo|hi], W'=[hi|hi|lo]
#define NCH   64
#define CHUNK 128             // NCH * CHUNK == TT

// GEMM tiling (Ampere-style mma.sync), BK=64, swizzled 128B rows
#define BM     128
#define BN     128
#define BK     64
#define ROWB   128                      // bytes per row (64 bf16), XOR-swizzled
#define TILE_SZ (BM * ROWB)             // 16384 B
#define STG_SZ  (2 * TILE_SZ)           // A tile + B tile = 32768 B
#define NSTG    3
#define NCHUNKS (KP / BK)               // 48
#define SMEM_DYN (NSTG * STG_SZ)        // 98304 B

// -------- scratch (device globals; no runtime allocation allowed) --------
__device__ __nv_bfloat16 g_a   [(size_t)MROWS * KP];   // ln output, split layout
__device__ __nv_bfloat16 g_att2[(size_t)MROWS * KP];   // attention, split layout
__device__ __nv_bfloat16 g_w   [(size_t)4 * CC * KP];  // Wk,Wv,Wr,Wo split layout
__device__ float g_k  [(size_t)MROWS * CC];
__device__ float g_v  [(size_t)MROWS * CC];
__device__ float g_r  [(size_t)MROWS * CC];
__device__ float g_csum[(size_t)BB * NCH * CC];

// ----------------------------- PTX helpers -----------------------------
__device__ __forceinline__ uint32_t smem_u32(const void* p) {
    uint32_t a;
    asm("{ .reg .u64 t; cvta.to.shared.u64 t, %1; cvt.u32.u64 %0, t; }" : "=r"(a) : "l"(p));
    return a;
}
__device__ __forceinline__ void cp16(uint32_t dst, const void* src) {
    asm volatile("cp.async.cg.shared.global [%0], [%1], 16;" :: "r"(dst), "l"(src));
}
__device__ __forceinline__ void cp_commit() {
    asm volatile("cp.async.commit_group;" ::: "memory");
}
__device__ __forceinline__ void cp_wait1() {
    asm volatile("cp.async.wait_group 1;" ::: "memory");
}
__device__ __forceinline__ void ldm_x4(uint32_t* f, uint32_t addr) {
    asm volatile("ldmatrix.sync.aligned.m8n8.x4.shared.b16 {%0,%1,%2,%3}, [%4];"
                 : "=r"(f[0]), "=r"(f[1]), "=r"(f[2]), "=r"(f[3]) : "r"(addr));
}
__device__ __forceinline__ void mma16816(float* c, const uint32_t* a, const uint32_t* b) {
    asm volatile("mma.sync.aligned.m16n8k16.row.col.f32.bf16.bf16.f32 "
                 "{%0,%1,%2,%3}, {%4,%5,%6,%7}, {%8,%9}, {%0,%1,%2,%3};"
                 : "+f"(c[0]), "+f"(c[1]), "+f"(c[2]), "+f"(c[3])
                 : "r"(a[0]), "r"(a[1]), "r"(a[2]), "r"(a[3]), "r"(b[0]), "r"(b[1]));
}

// ======================= LayerNorm -> split bf16 layout =======================
__global__ void ln_kernel(const float* __restrict__ x,
                          const float* __restrict__ ln_w,
                          const float* __restrict__ ln_b) {
    int gwarp = (blockIdx.x * blockDim.x + threadIdx.x) >> 5;
    int lane  = threadIdx.x & 31;
    if (gwarp >= MROWS) return;

    const float4* xr = (const float4*)(x + (size_t)gwarp * CC);
    const float4* wr = (const float4*)ln_w;
    const float4* br = (const float4*)ln_b;

    float4 vals[8];
    float s = 0.f, s2 = 0.f;
#pragma unroll
    for (int i = 0; i < 8; i++) {
        float4 v = xr[lane + i * 32];
        vals[i] = v;
        s  += v.x + v.y + v.z + v.w;
        s2 += v.x * v.x + v.y * v.y + v.z * v.z + v.w * v.w;
    }
#pragma unroll
    for (int off = 16; off; off >>= 1) {
        s  += __shfl_xor_sync(0xffffffffu, s,  off);
        s2 += __shfl_xor_sync(0xffffffffu, s2, off);
    }
    const float inv = 1.0f / (float)CC;
    float mu  = s * inv;
    float var = s2 * inv - mu * mu;
    float rstd = rsqrtf(var + 1e-5f);

    __nv_bfloat16* arow = g_a + (size_t)gwarp * KP;
#pragma unroll
    for (int i = 0; i < 8; i++) {
        float4 v = vals[i];
        float4 w = wr[lane + i * 32];
        float4 b = br[lane + i * 32];
        float o0 = (v.x - mu) * rstd * w.x + b.x;
        float o1 = (v.y - mu) * rstd * w.y + b.y;
        float o2 = (v.z - mu) * rstd * w.z + b.z;
        float o3 = (v.w - mu) * rstd * w.w + b.w;
        __nv_bfloat16 h0 = __float2bfloat16_rn(o0);
        __nv_bfloat16 h1 = __float2bfloat16_rn(o1);
        __nv_bfloat16 h2 = __float2bfloat16_rn(o2);
        __nv_bfloat16 h3 = __float2bfloat16_rn(o3);
        __nv_bfloat16 l0 = __float2bfloat16_rn(o0 - __bfloat162float(h0));
        __nv_bfloat16 l1 = __float2bfloat16_rn(o1 - __bfloat162float(h1));
        __nv_bfloat16 l2 = __float2bfloat16_rn(o2 - __bfloat162float(h2));
        __nv_bfloat16 l3 = __float2bfloat16_rn(o3 - __bfloat162float(h3));
        int col = (lane + i * 32) * 4;
        __nv_bfloat162 H0; H0.x = h0; H0.y = h1;
        __nv_bfloat162 H1; H1.x = h2; H1.y = h3;
        __nv_bfloat162 L0; L0.x = l0; L0.y = l1;
        __nv_bfloat162 L1; L1.x = l2; L1.y = l3;
        *(__nv_bfloat162*)(arow + col)            = H0;
        *(__nv_bfloat162*)(arow + col + 2)        = H1;
        *(__nv_bfloat162*)(arow + 1024 + col)     = L0;
        *(__nv_bfloat162*)(arow + 1024 + col + 2) = L1;
        *(__nv_bfloat162*)(arow + 2048 + col)     = H0;
        *(__nv_bfloat162*)(arow + 2048 + col + 2) = H1;
    }
}

// =================== weight conversion to split bf16 layout ===================
__global__ void wconv(const float* __restrict__ Wk, const float* __restrict__ Wv,
                      const float* __restrict__ Wr, const float* __restrict__ Wo) {
    size_t idx  = (size_t)blockIdx.x * blockDim.x + threadIdx.x;
    size_t base = idx * 4;
    int w = (int)(base >> 20);
    size_t rem = base & 0xFFFFFu;
    const float* W = (w == 0) ? Wk : (w == 1) ? Wv : (w == 2) ? Wr : Wo;
    float4 v = *(const float4*)(W + rem);
    __nv_bfloat16 h0 = __float2bfloat16_rn(v.x);
    __nv_bfloat16 h1 = __float2bfloat16_rn(v.y);
    __nv_bfloat16 h2 = __float2bfloat16_rn(v.z);
    __nv_bfloat16 h3 = __float2bfloat16_rn(v.w);
    __nv_bfloat16 l0 = __float2bfloat16_rn(v.x - __bfloat162float(h0));
    __nv_bfloat16 l1 = __float2bfloat16_rn(v.y - __bfloat162float(h1));
    __nv_bfloat16 l2 = __float2bfloat16_rn(v.z - __bfloat162float(h2));
    __nv_bfloat16 l3 = __float2bfloat16_rn(v.w - __bfloat162float(h3));
    size_t row = rem >> 10;
    size_t k   = rem & 1023u;
    __nv_bfloat16* dst = g_w + ((size_t)w * CC + row) * KP + k;
    __nv_bfloat162 H0; H0.x = h0; H0.y = h1;
    __nv_bfloat162 H1; H1.x = h2; H1.y = h3;
    __nv_bfloat162 L0; L0.x = l0; L0.y = l1;
    __nv_bfloat162 L1; L1.x = l2; L1.y = l3;
    *(__nv_bfloat162*)(dst)            = H0;
    *(__nv_bfloat162*)(dst + 2)        = H1;
    *(__nv_bfloat162*)(dst + 1024)     = H0;
    *(__nv_bfloat162*)(dst + 1024 + 2) = H1;
    *(__nv_bfloat162*)(dst + 2048)     = L0;
    *(__nv_bfloat162*)(dst + 2048 + 2) = L1;
}

// ============== bf16 mma.sync NT GEMM: C[M,N] = A'[M,KP] * W'[N,KP]^T ==============
// BK=64, XOR-swizzled 128B smem rows, ldmatrix x4 for A and B.
__global__ void __launch_bounds__(256, 2)
gemm_mma(float* __restrict__ out, int isKVR) {
    extern __shared__ __align__(1024) char smem[];
    const uint32_t sbase = smem_u32(smem);

    const int tid  = threadIdx.x;
    const int lane = tid & 31;
    const int wid  = tid >> 5;
    const int wm   = wid & 1;     // 2 warp-rows (64 each)
    const int wn   = wid >> 1;    // 4 warp-cols (32 each)

    int col, w;
    if (isKVR) { w = blockIdx.x % 3; col = blockIdx.x / 3; }
    else       { w = 3;              col = blockIdx.x;     }
    const int brow = blockIdx.y * BM;
    const int bcol = col * BN;

    const __nv_bfloat16* Abase = (isKVR ? g_a : g_att2) + (size_t)brow * KP;
    const __nv_bfloat16* Wbase = g_w + ((size_t)w * CC + bcol) * KP;

    // ldmatrix per-lane swizzled address components.
    // A (x4 per m-tile): rowA = wm*64 + mt*16 + (lane&15); chunk = kh*2 + (lane>>4)
    uint32_t abase[4], axor[4];
#pragma unroll
    for (int mt = 0; mt < 4; mt++) {
        int rowA = wm * 64 + mt * 16 + (lane & 15);
        int s = rowA & 7;
        abase[mt] = (uint32_t)(rowA * ROWB + (((lane >> 4) ^ (s & 1)) << 4));
        axor[mt]  = (uint32_t)((s & 6) << 4);
    }
    // B (x4 per n-tile-pair): rowB = wn*32 + ntp*16 + (lane>>4)*8 + (lane&7);
    // chunk = kh*2 + ((lane>>3)&1)
    uint32_t bbase[2], bxor[2];
#pragma unroll
    for (int ntp = 0; ntp < 2; ntp++) {
        int rowB = wn * 32 + ntp * 16 + ((lane >> 4) << 3) + (lane & 7);
        int s = rowB & 7;
        bbase[ntp] = (uint32_t)(rowB * ROWB + ((((lane >> 3) & 1) ^ (s & 1)) << 4));
        bxor[ntp]  = (uint32_t)((s & 6) << 4);
    }

    float acc[4][4][4];
#pragma unroll
    for (int mt = 0; mt < 4; mt++)
#pragma unroll
        for (int nt = 0; nt < 4; nt++)
#pragma unroll
            for (int j = 0; j < 4; j++) acc[mt][nt][j] = 0.f;

    // ---- async load of one stage (BK=64: 8 chunks of 16B per row) ----
    auto load_stage = [&](int stg, int chunk) {
        uint32_t sA = sbase + stg * STG_SZ;
        uint32_t sB = sA + TILE_SZ;
        const __nv_bfloat16* Ap = Abase + chunk * BK;
        const __nv_bfloat16* Wp = Wbase + chunk * BK;
#pragma unroll
        for (int t = tid; t < 1024; t += 256) {
            int r = t >> 3, c = t & 7;
            uint32_t off = (uint32_t)(r * ROWB + ((c ^ (r & 7)) << 4));
            cp16(sA + off, Ap + (size_t)r * KP + c * 8);
            cp16(sB + off, Wp + (size_t)r * KP + c * 8);
        }
    };

    load_stage(0, 0); cp_commit();
    load_stage(1, 1); cp_commit();

    for (int i = 0; i < NCHUNKS; i++) {
        cp_wait1();
        __syncthreads();
        if (i + 2 < NCHUNKS) load_stage((i + 2) % NSTG, i + 2);
        cp_commit();

        uint32_t sA = sbase + (i % NSTG) * STG_SZ;
        uint32_t sB = sA + TILE_SZ;
#pragma unroll
        for (int kh = 0; kh < 4; kh++) {
            uint32_t kb = (uint32_t)(kh * 32);
            uint32_t af[4][4], bf[4][2];
#pragma unroll
            for (int mt = 0; mt < 4; mt++)
                ldm_x4(af[mt], sA + abase[mt] + (kb ^ axor[mt]));
#pragma unroll
            for (int ntp = 0; ntp < 2; ntp++) {
                uint32_t t4[4];
                ldm_x4(t4, sB + bbase[ntp] + (kb ^ bxor[ntp]));
                bf[ntp * 2 + 0][0] = t4[0]; bf[ntp * 2 + 0][1] = t4[1];
                bf[ntp * 2 + 1][0] = t4[2]; bf[ntp * 2 + 1][1] = t4[3];
            }
#pragma unroll
            for (int mt = 0; mt < 4; mt++)
#pragma unroll
                for (int nt = 0; nt < 4; nt++)
                    mma16816(acc[mt][nt], af[mt], bf[nt]);
        }
    }

    // ---- epilogue: fp32 direct to global ----
    float* Cm;
    if (isKVR) Cm = (w == 0) ? g_k : (w == 1) ? g_v : g_r;
    else       Cm = out;
    const int r0 = brow + wm * 64 + (lane >> 2);
    const int c0 = bcol + wn * 32 + (lane & 3) * 2;
#pragma unroll
    for (int mt = 0; mt < 4; mt++) {
#pragma unroll
        for (int nt = 0; nt < 4; nt++) {
            float* p0 = Cm + (size_t)(r0 + mt * 16) * CC + c0 + nt * 8;
            float* p1 = p0 + 8 * CC;
            *(float2*)p0 = make_float2(acc[mt][nt][0], acc[mt][nt][1]);
            *(float2*)p1 = make_float2(acc[mt][nt][2], acc[mt][nt][3]);
        }
    }
}

// ======================= WKV scan (chunked 2-pass) =======================
__global__ void scan_partial(const float* __restrict__ time_decay) {
    int c  = blockIdx.x * 256 + threadIdx.x;
    int ch = blockIdx.y;
    int b  = blockIdx.z;
    float td = -expf(time_decay[c]);
    size_t base = ((size_t)(b * TT + ch * CHUNK)) * CC + c;
    float s = 0.f;
#pragma unroll 4
    for (int i = 0; i < CHUNK; i++) {
        float t = (float)(ch * CHUNK + i);
        float w = expf(td * t);
        size_t id = base + (size_t)i * CC;
        s += g_k[id] * g_v[id] * w;
    }
    g_csum[((size_t)b * NCH + ch) * CC + c] = s;
}

// pass 2: inline exclusive chunk-prefix + replay; writes split-bf16 att
__global__ void scan_final(const float* __restrict__ time_decay,
                           const float* __restrict__ time_first) {
    int c  = blockIdx.x * 256 + threadIdx.x;
    int ch = blockIdx.y;
    int b  = blockIdx.z;
    float td = -expf(time_decay[c]);
    float tf = expf(time_first[c]);

    float state = 0.f;
    for (int j = 0; j < ch; j++)
        state += g_csum[((size_t)b * NCH + j) * CC + c];

    size_t rowbase = (size_t)(b * TT + ch * CHUNK);
#pragma unroll 4
    for (int i = 0; i < CHUNK; i++) {
        size_t id = (rowbase + i) * CC + c;
        float kk = g_k[id];
        float vv = g_v[id];
        float rr = g_r[id];
        float wgt = expf(td * (float)(ch * CHUNK + i));
        float sig = 1.0f / (1.0f + expf(-rr));
        float av  = sig * (state + kk * tf);
        state += kk * vv * wgt;
        __nv_bfloat16 h = __float2bfloat16_rn(av);
        __nv_bfloat16 l = __float2bfloat16_rn(av - __bfloat162float(h));
        __nv_bfloat16* arow = g_att2 + (rowbase + i) * KP + c;
        arow[0]    = h;
        arow[1024] = l;
        arow[2048] = h;
    }
}

// ================================ launch ================================
extern "C" void kernel_launch(void* const* d_in, const int* in_sizes, int n_in,
                              void* d_out, int out_size) {
    const float* x          = (const float*)d_in[0];
    const float* time_decay = (const float*)d_in[1];
    const float* time_first = (const float*)d_in[2];
    const float* Wk         = (const float*)d_in[3];
    const float* Wv         = (const float*)d_in[4];
    const float* Wr         = (const float*)d_in[5];
    const float* Wo         = (const float*)d_in[6];
    const float* ln_w       = (const float*)d_in[7];
    const float* ln_b       = (const float*)d_in[8];
    float* out = (float*)d_out;

    cudaFuncSetAttribute(gemm_mma, cudaFuncAttributeMaxDynamicSharedMemorySize, SMEM_DYN);

    // 1) LayerNorm -> g_a (split bf16); weights -> g_w (split bf16)
    ln_kernel<<<MROWS / 8, 256>>>(x, ln_w, ln_b);
    wconv<<<4096, 256>>>(Wk, Wv, Wr, Wo);

    // 2) k, v, r projections (fused: blockIdx.x = col*3 + weight, w fastest for L2 reuse)
    gemm_mma<<<dim3(24, MROWS / BM), 256, SMEM_DYN>>>(nullptr, 1);

    // 3) WKV scan (2-pass; final inlines the chunk-prefix)
    scan_partial<<<dim3(CC / 256, NCH, BB), 256>>>(time_decay);
    scan_final<<<dim3(CC / 256, NCH, BB), 256>>>(time_decay, time_first);

    // 4) output projection -> d_out   (6th launch: ncu -s 5 captures this)
    gemm_mma<<<dim3(8, MROWS / BM), 256, SMEM_DYN>>>(out, 0);
}

// round 7
// speedup vs baseline: 4.5362x; 1.4207x over previous
#include <cuda_runtime.h>
#include <cuda_fp16.h>
#include <math.h>
#include <stdint.h>

// ----------------------------- problem constants -----------------------------
#define BB    4
#define TT    8192
#define CC    1024
#define MROWS (BB * TT)       // 32768
#define KP    2048            // split-K: A'=[hi|lo] (fp16), W'=[hi|hi]
#define NCH   64
#define CHUNK 128             // NCH * CHUNK == TT

// GEMM tiling (mma.sync m16n8k16 f16), BK=64, swizzled 128B rows
#define BM     128
#define BN     128
#define BK     64
#define ROWB   128                      // bytes per row (64 fp16), XOR-swizzled
#define TILE_SZ (BM * ROWB)             // 16384 B
#define STG_SZ  (2 * TILE_SZ)           // A tile + B tile = 32768 B
#define NSTG    3
#define NCHUNKS (KP / BK)               // 32
#define SMEM_DYN (NSTG * STG_SZ)        // 98304 B

// -------- scratch (device globals; no runtime allocation allowed) --------
__device__ __half g_a   [(size_t)MROWS * KP];   // ln output, split layout
__device__ __half g_att2[(size_t)MROWS * KP];   // attention, split layout
__device__ __half g_w   [(size_t)4 * CC * KP];  // Wk,Wv,Wr,Wo split layout
__device__ float g_k  [(size_t)MROWS * CC];
__device__ float g_v  [(size_t)MROWS * CC];
__device__ float g_r  [(size_t)MROWS * CC];
__device__ float g_csum[(size_t)BB * NCH * CC];

// ----------------------------- PTX helpers -----------------------------
__device__ __forceinline__ uint32_t smem_u32(const void* p) {
    uint32_t a;
    asm("{ .reg .u64 t; cvta.to.shared.u64 t, %1; cvt.u32.u64 %0, t; }" : "=r"(a) : "l"(p));
    return a;
}
__device__ __forceinline__ void cp16(uint32_t dst, const void* src) {
    asm volatile("cp.async.cg.shared.global [%0], [%1], 16;" :: "r"(dst), "l"(src));
}
__device__ __forceinline__ void cp_commit() {
    asm volatile("cp.async.commit_group;" ::: "memory");
}
__device__ __forceinline__ void cp_wait1() {
    asm volatile("cp.async.wait_group 1;" ::: "memory");
}
__device__ __forceinline__ void ldm_x4(uint32_t* f, uint32_t addr) {
    asm volatile("ldmatrix.sync.aligned.m8n8.x4.shared.b16 {%0,%1,%2,%3}, [%4];"
                 : "=r"(f[0]), "=r"(f[1]), "=r"(f[2]), "=r"(f[3]) : "r"(addr));
}
__device__ __forceinline__ void mma16816(float* c, const uint32_t* a, const uint32_t* b) {
    asm volatile("mma.sync.aligned.m16n8k16.row.col.f32.f16.f16.f32 "
                 "{%0,%1,%2,%3}, {%4,%5,%6,%7}, {%8,%9}, {%0,%1,%2,%3};"
                 : "+f"(c[0]), "+f"(c[1]), "+f"(c[2]), "+f"(c[3])
                 : "r"(a[0]), "r"(a[1]), "r"(a[2]), "r"(a[3]), "r"(b[0]), "r"(b[1]));
}

// ======================= LayerNorm -> split fp16 layout =======================
__global__ void ln_kernel(const float* __restrict__ x,
                          const float* __restrict__ ln_w,
                          const float* __restrict__ ln_b) {
    int gwarp = (blockIdx.x * blockDim.x + threadIdx.x) >> 5;
    int lane  = threadIdx.x & 31;
    if (gwarp >= MROWS) return;

    const float4* xr = (const float4*)(x + (size_t)gwarp * CC);
    const float4* wr = (const float4*)ln_w;
    const float4* br = (const float4*)ln_b;

    float4 vals[8];
    float s = 0.f, s2 = 0.f;
#pragma unroll
    for (int i = 0; i < 8; i++) {
        float4 v = xr[lane + i * 32];
        vals[i] = v;
        s  += v.x + v.y + v.z + v.w;
        s2 += v.x * v.x + v.y * v.y + v.z * v.z + v.w * v.w;
    }
#pragma unroll
    for (int off = 16; off; off >>= 1) {
        s  += __shfl_xor_sync(0xffffffffu, s,  off);
        s2 += __shfl_xor_sync(0xffffffffu, s2, off);
    }
    const float inv = 1.0f / (float)CC;
    float mu  = s * inv;
    float var = s2 * inv - mu * mu;
    float rstd = rsqrtf(var + 1e-5f);

    __half* arow = g_a + (size_t)gwarp * KP;
#pragma unroll
    for (int i = 0; i < 8; i++) {
        float4 v = vals[i];
        float4 w = wr[lane + i * 32];
        float4 b = br[lane + i * 32];
        float o0 = (v.x - mu) * rstd * w.x + b.x;
        float o1 = (v.y - mu) * rstd * w.y + b.y;
        float o2 = (v.z - mu) * rstd * w.z + b.z;
        float o3 = (v.w - mu) * rstd * w.w + b.w;
        __half h0 = __float2half_rn(o0);
        __half h1 = __float2half_rn(o1);
        __half h2 = __float2half_rn(o2);
        __half h3 = __float2half_rn(o3);
        __half l0 = __float2half_rn(o0 - __half2float(h0));
        __half l1 = __float2half_rn(o1 - __half2float(h1));
        __half l2 = __float2half_rn(o2 - __half2float(h2));
        __half l3 = __float2half_rn(o3 - __half2float(h3));
        int col = (lane + i * 32) * 4;
        __half2 H0 = __halves2half2(h0, h1);
        __half2 H1 = __halves2half2(h2, h3);
        __half2 L0 = __halves2half2(l0, l1);
        __half2 L1 = __halves2half2(l2, l3);
        *(__half2*)(arow + col)            = H0;
        *(__half2*)(arow + col + 2)        = H1;
        *(__half2*)(arow + 1024 + col)     = L0;
        *(__half2*)(arow + 1024 + col + 2) = L1;
    }
}

// =================== weight conversion to split fp16 layout ===================
// W'=[hi|hi] : pairs with A'=[hi|lo] so that (ahi+alo)*whi is computed.
__global__ void wconv(const float* __restrict__ Wk, const float* __restrict__ Wv,
                      const float* __restrict__ Wr, const float* __restrict__ Wo) {
    size_t idx  = (size_t)blockIdx.x * blockDim.x + threadIdx.x;
    size_t base = idx * 4;
    int w = (int)(base >> 20);
    size_t rem = base & 0xFFFFFu;
    const float* W = (w == 0) ? Wk : (w == 1) ? Wv : (w == 2) ? Wr : Wo;
    float4 v = *(const float4*)(W + rem);
    __half h0 = __float2half_rn(v.x);
    __half h1 = __float2half_rn(v.y);
    __half h2 = __float2half_rn(v.z);
    __half h3 = __float2half_rn(v.w);
    size_t row = rem >> 10;
    size_t k   = rem & 1023u;
    __half* dst = g_w + ((size_t)w * CC + row) * KP + k;
    __half2 H0 = __halves2half2(h0, h1);
    __half2 H1 = __halves2half2(h2, h3);
    *(__half2*)(dst)            = H0;
    *(__half2*)(dst + 2)        = H1;
    *(__half2*)(dst + 1024)     = H0;
    *(__half2*)(dst + 1024 + 2) = H1;
}

// ============== fp16 mma.sync NT GEMM: C[M,N] = A'[M,KP] * W'[N,KP]^T ==============
// BK=64, XOR-swizzled 128B smem rows, ldmatrix x4 for A and B.
__global__ void __launch_bounds__(256, 2)
gemm_mma(float* __restrict__ out, int isKVR) {
    extern __shared__ __align__(1024) char smem[];
    const uint32_t sbase = smem_u32(smem);

    const int tid  = threadIdx.x;
    const int lane = tid & 31;
    const int wid  = tid >> 5;
    const int wm   = wid & 1;     // 2 warp-rows (64 each)
    const int wn   = wid >> 1;    // 4 warp-cols (32 each)

    int col, w;
    if (isKVR) { w = blockIdx.x % 3; col = blockIdx.x / 3; }
    else       { w = 3;              col = blockIdx.x;     }
    const int brow = blockIdx.y * BM;
    const int bcol = col * BN;

    const __half* Abase = (isKVR ? g_a : g_att2) + (size_t)brow * KP;
    const __half* Wbase = g_w + ((size_t)w * CC + bcol) * KP;

    // ldmatrix per-lane swizzled address components.
    uint32_t abase[4], axor[4];
#pragma unroll
    for (int mt = 0; mt < 4; mt++) {
        int rowA = wm * 64 + mt * 16 + (lane & 15);
        int s = rowA & 7;
        abase[mt] = (uint32_t)(rowA * ROWB + (((lane >> 4) ^ (s & 1)) << 4));
        axor[mt]  = (uint32_t)((s & 6) << 4);
    }
    uint32_t bbase[2], bxor[2];
#pragma unroll
    for (int ntp = 0; ntp < 2; ntp++) {
        int rowB = wn * 32 + ntp * 16 + ((lane >> 4) << 3) + (lane & 7);
        int s = rowB & 7;
        bbase[ntp] = (uint32_t)(rowB * ROWB + ((((lane >> 3) & 1) ^ (s & 1)) << 4));
        bxor[ntp]  = (uint32_t)((s & 6) << 4);
    }

    float acc[4][4][4];
#pragma unroll
    for (int mt = 0; mt < 4; mt++)
#pragma unroll
        for (int nt = 0; nt < 4; nt++)
#pragma unroll
            for (int j = 0; j < 4; j++) acc[mt][nt][j] = 0.f;

    // ---- async load of one stage (BK=64: 8 chunks of 16B per row) ----
    auto load_stage = [&](int stg, int chunk) {
        uint32_t sA = sbase + stg * STG_SZ;
        uint32_t sB = sA + TILE_SZ;
        const __half* Ap = Abase + chunk * BK;
        const __half* Wp = Wbase + chunk * BK;
#pragma unroll
        for (int t = tid; t < 1024; t += 256) {
            int r = t >> 3, c = t & 7;
            uint32_t off = (uint32_t)(r * ROWB + ((c ^ (r & 7)) << 4));
            cp16(sA + off, Ap + (size_t)r * KP + c * 8);
            cp16(sB + off, Wp + (size_t)r * KP + c * 8);
        }
    };

    load_stage(0, 0); cp_commit();
    load_stage(1, 1); cp_commit();

    for (int i = 0; i < NCHUNKS; i++) {
        cp_wait1();
        __syncthreads();
        if (i + 2 < NCHUNKS) load_stage((i + 2) % NSTG, i + 2);
        cp_commit();

        uint32_t sA = sbase + (i % NSTG) * STG_SZ;
        uint32_t sB = sA + TILE_SZ;
#pragma unroll
        for (int kh = 0; kh < 4; kh++) {
            uint32_t kb = (uint32_t)(kh * 32);
            uint32_t af[4][4], bf[4][2];
#pragma unroll
            for (int mt = 0; mt < 4; mt++)
                ldm_x4(af[mt], sA + abase[mt] + (kb ^ axor[mt]));
#pragma unroll
            for (int ntp = 0; ntp < 2; ntp++) {
                uint32_t t4[4];
                ldm_x4(t4, sB + bbase[ntp] + (kb ^ bxor[ntp]));
                bf[ntp * 2 + 0][0] = t4[0]; bf[ntp * 2 + 0][1] = t4[1];
                bf[ntp * 2 + 1][0] = t4[2]; bf[ntp * 2 + 1][1] = t4[3];
            }
#pragma unroll
            for (int mt = 0; mt < 4; mt++)
#pragma unroll
                for (int nt = 0; nt < 4; nt++)
                    mma16816(acc[mt][nt], af[mt], bf[nt]);
        }
    }

    // ---- epilogue: fp32 direct to global ----
    float* Cm;
    if (isKVR) Cm = (w == 0) ? g_k : (w == 1) ? g_v : g_r;
    else       Cm = out;
    const int r0 = brow + wm * 64 + (lane >> 2);
    const int c0 = bcol + wn * 32 + (lane & 3) * 2;
#pragma unroll
    for (int mt = 0; mt < 4; mt++) {
#pragma unroll
        for (int nt = 0; nt < 4; nt++) {
            float* p0 = Cm + (size_t)(r0 + mt * 16) * CC + c0 + nt * 8;
            float* p1 = p0 + 8 * CC;
            *(float2*)p0 = make_float2(acc[mt][nt][0], acc[mt][nt][1]);
            *(float2*)p1 = make_float2(acc[mt][nt][2], acc[mt][nt][3]);
        }
    }
}

// ======================= WKV scan (chunked 2-pass) =======================
__global__ void scan_partial(const float* __restrict__ time_decay) {
    int c  = blockIdx.x * 256 + threadIdx.x;
    int ch = blockIdx.y;
    int b  = blockIdx.z;
    float td = -expf(time_decay[c]);
    size_t base = ((size_t)(b * TT + ch * CHUNK)) * CC + c;
    float s = 0.f;
#pragma unroll 4
    for (int i = 0; i < CHUNK; i++) {
        float t = (float)(ch * CHUNK + i);
        float w = expf(td * t);
        size_t id = base + (size_t)i * CC;
        s += g_k[id] * g_v[id] * w;
    }
    g_csum[((size_t)b * NCH + ch) * CC + c] = s;
}

// pass 2: inline exclusive chunk-prefix + replay; writes split-fp16 att
__global__ void scan_final(const float* __restrict__ time_decay,
                           const float* __restrict__ time_first) {
    int c  = blockIdx.x * 256 + threadIdx.x;
    int ch = blockIdx.y;
    int b  = blockIdx.z;
    float td = -expf(time_decay[c]);
    float tf = expf(time_first[c]);

    float state = 0.f;
    for (int j = 0; j < ch; j++)
        state += g_csum[((size_t)b * NCH + j) * CC + c];

    size_t rowbase = (size_t)(b * TT + ch * CHUNK);
#pragma unroll 4
    for (int i = 0; i < CHUNK; i++) {
        size_t id = (rowbase + i) * CC + c;
        float kk = g_k[id];
        float vv = g_v[id];
        float rr = g_r[id];
        float wgt = expf(td * (float)(ch * CHUNK + i));
        float sig = 1.0f / (1.0f + expf(-rr));
        float av  = sig * (state + kk * tf);
        state += kk * vv * wgt;
        __half h = __float2half_rn(av);
        __half l = __float2half_rn(av - __half2float(h));
        __half* arow = g_att2 + (rowbase + i) * KP + c;
        arow[0]    = h;
        arow[1024] = l;
    }
}

// ================================ launch ================================
extern "C" void kernel_launch(void* const* d_in, const int* in_sizes, int n_in,
                              void* d_out, int out_size) {
    const float* x          = (const float*)d_in[0];
    const float* time_decay = (const float*)d_in[1];
    const float* time_first = (const float*)d_in[2];
    const float* Wk         = (const float*)d_in[3];
    const float* Wv         = (const float*)d_in[4];
    const float* Wr         = (const float*)d_in[5];
    const float* Wo         = (const float*)d_in[6];
    const float* ln_w       = (const float*)d_in[7];
    const float* ln_b       = (const float*)d_in[8];
    float* out = (float*)d_out;

    cudaFuncSetAttribute(gemm_mma, cudaFuncAttributeMaxDynamicSharedMemorySize, SMEM_DYN);

    // 1) LayerNorm -> g_a (split fp16); weights -> g_w (split fp16)
    ln_kernel<<<MROWS / 8, 256>>>(x, ln_w, ln_b);
    wconv<<<4096, 256>>>(Wk, Wv, Wr, Wo);

    // 2) k, v, r projections (fused: blockIdx.x = col*3 + weight, w fastest for L2 reuse)
    gemm_mma<<<dim3(24, MROWS / BM), 256, SMEM_DYN>>>(nullptr, 1);

    // 3) WKV scan (2-pass; final inlines the chunk-prefix)
    scan_partial<<<dim3(CC / 256, NCH, BB), 256>>>(time_decay);
    scan_final<<<dim3(CC / 256, NCH, BB), 256>>>(time_decay, time_first);

    // 4) output projection -> d_out
    gemm_mma<<<dim3(8, MROWS / BM), 256, SMEM_DYN>>>(out, 0);
}